// round 6
// baseline (speedup 1.0000x reference)
#include <cuda_runtime.h>
#include <cuda_bf16.h>
#include <cfloat>
#include <cstdint>

// ---------------------------------------------------------------------------
// EmbeddingBag mean||max (B=8192 bags over T=409600 tokens, D=128) + Linear
//   feature_seq : int32 [T]
//   offset_seq  : int32 [B]   (sorted bag starts, offs[0]==0)
//   W           : f32   [VOCAB, 128]
//   L           : f32   [128, 256]
//   out         : f32   [B, 128] = concat(mean, max) @ L^T
// ---------------------------------------------------------------------------

#define D 128
#define K2 256
#define MAX_B 8192

__device__ __align__(16) float g_men[MAX_B * K2];   // [B, 256] scratch

// ============================================================================
// Kernel 1: block-per-bag, 8 warps take contiguous chunks; smem combine.
// At the chip L2-bandwidth floor (~220MB through LTS).
// ============================================================================
__global__ void __launch_bounds__(256) bag_reduce_kernel(
    const int* __restrict__ feat,
    const int* __restrict__ offs,
    const float* __restrict__ W,
    int T, int B)
{
    const int bag  = blockIdx.x;
    const int w    = threadIdx.x >> 5;
    const int lane = threadIdx.x & 31;

    const int start = offs[bag];
    const int end   = (bag == B - 1) ? T : offs[bag + 1];
    const int cnt   = end - start;

    const float4* __restrict__ Wv = (const float4*)W;   // row stride = 32 float4

    float4 s = make_float4(0.f, 0.f, 0.f, 0.f);
    float4 m = make_float4(-FLT_MAX, -FLT_MAX, -FLT_MAX, -FLT_MAX);

    const int chunk = (cnt + 7) >> 3;
    const int cs = start + w * chunk;
    const int ce = min(cs + chunk, end);

    int t = cs;
    for (; t + 4 <= ce; t += 4) {
        const int f0 = __ldg(&feat[t + 0]);
        const int f1 = __ldg(&feat[t + 1]);
        const int f2 = __ldg(&feat[t + 2]);
        const int f3 = __ldg(&feat[t + 3]);
        const float4 v0 = __ldg(&Wv[f0 * 32 + lane]);
        const float4 v1 = __ldg(&Wv[f1 * 32 + lane]);
        const float4 v2 = __ldg(&Wv[f2 * 32 + lane]);
        const float4 v3 = __ldg(&Wv[f3 * 32 + lane]);
        s.x += v0.x + v1.x + v2.x + v3.x;
        s.y += v0.y + v1.y + v2.y + v3.y;
        s.z += v0.z + v1.z + v2.z + v3.z;
        s.w += v0.w + v1.w + v2.w + v3.w;
        m.x = fmaxf(m.x, fmaxf(fmaxf(v0.x, v1.x), fmaxf(v2.x, v3.x)));
        m.y = fmaxf(m.y, fmaxf(fmaxf(v0.y, v1.y), fmaxf(v2.y, v3.y)));
        m.z = fmaxf(m.z, fmaxf(fmaxf(v0.z, v1.z), fmaxf(v2.z, v3.z)));
        m.w = fmaxf(m.w, fmaxf(fmaxf(v0.w, v1.w), fmaxf(v2.w, v3.w)));
    }
    for (; t < ce; ++t) {
        const int f = __ldg(&feat[t]);
        const float4 v = __ldg(&Wv[f * 32 + lane]);
        s.x += v.x; s.y += v.y; s.z += v.z; s.w += v.w;
        m.x = fmaxf(m.x, v.x); m.y = fmaxf(m.y, v.y);
        m.z = fmaxf(m.z, v.z); m.w = fmaxf(m.w, v.w);
    }

    __shared__ float4 Ss[8][32];
    __shared__ float4 Sm[8][32];
    Ss[w][lane] = s;
    Sm[w][lane] = m;
    __syncthreads();

    if (threadIdx.x < 32) {
        float4 rs = Ss[0][lane];
        float4 rm = Sm[0][lane];
#pragma unroll
        for (int i = 1; i < 8; ++i) {
            const float4 a = Ss[i][lane];
            const float4 b = Sm[i][lane];
            rs.x += a.x; rs.y += a.y; rs.z += a.z; rs.w += a.w;
            rm.x = fmaxf(rm.x, b.x); rm.y = fmaxf(rm.y, b.y);
            rm.z = fmaxf(rm.z, b.z); rm.w = fmaxf(rm.w, b.w);
        }
        const float inv = 1.0f / fmaxf((float)cnt, 1.0f);
        float4 mean = make_float4(rs.x * inv, rs.y * inv, rs.z * inv, rs.w * inv);
        if (cnt == 0) rm = make_float4(0.f, 0.f, 0.f, 0.f);

        float4* mp = (float4*)g_men;                 // row stride = 64 float4
        mp[bag * 64 + lane]      = mean;             // cols [0,128)
        mp[bag * 64 + 32 + lane] = rm;               // cols [128,256)
    }
}

// ============================================================================
// Kernel 2: C = men @ L^T. mma.sync m16n8k8 tf32.
// BM=32, BN=64, BK=32 -> 512 blocks (3.5/SM), 256 threads, ~28KB smem.
// 2-stage cp.async double buffer (raw f32 in smem; tf32 cvt at fragment load).
// 8 warps as 2x4; warp tile 16x16 = 1x2 mma tiles.
// ============================================================================
#define BM 32
#define BN 64
#define BK 32
#define LDA 36             // padded k-stride (words)

__device__ __forceinline__ uint32_t f2tf32(float f) {
    uint32_t r;
    asm("cvt.rna.tf32.f32 %0, %1;" : "=r"(r) : "f"(f));
    return r;
}

__device__ __forceinline__ void mma_tf32(float c[4],
                                         uint32_t a0, uint32_t a1, uint32_t a2, uint32_t a3,
                                         uint32_t b0, uint32_t b1) {
    asm volatile(
        "mma.sync.aligned.m16n8k8.row.col.f32.tf32.tf32.f32 "
        "{%0,%1,%2,%3}, {%4,%5,%6,%7}, {%8,%9}, {%0,%1,%2,%3};"
        : "+f"(c[0]), "+f"(c[1]), "+f"(c[2]), "+f"(c[3])
        : "r"(a0), "r"(a1), "r"(a2), "r"(a3), "r"(b0), "r"(b1));
}

__device__ __forceinline__ void cp_async16(void* smem_dst, const void* gmem_src) {
    uint32_t a;
    asm("{ .reg .u64 t; cvta.to.shared.u64 t, %1; cvt.u32.u64 %0, t; }"
        : "=r"(a) : "l"(smem_dst));
    asm volatile("cp.async.ca.shared.global [%0], [%1], 16;" :: "r"(a), "l"(gmem_src));
}
#define CP_COMMIT() asm volatile("cp.async.commit_group;" ::: "memory")
#define CP_WAIT1()  asm volatile("cp.async.wait_group 1;" ::: "memory")
#define CP_WAIT0()  asm volatile("cp.async.wait_group 0;" ::: "memory")

__global__ void __launch_bounds__(256) men_gemm_kernel(
    const float* __restrict__ L,
    float* __restrict__ out,
    int B)
{
    __shared__ float As[2][BM * LDA];   // raw f32
    __shared__ float Bs[2][BN * LDA];

    const int tid  = threadIdx.x;
    const int wid  = tid >> 5;
    const int lane = tid & 31;
    const int wr   = wid & 1;           // warp row 0..1 (16 rows each)
    const int wc   = wid >> 1;          // warp col 0..3 (16 cols each)
    const int gp   = lane >> 2;
    const int tg   = lane & 3;
    const int brow0 = blockIdx.x * BM;
    const int bcol0 = blockIdx.y * BN;

    // stage loader: A 32x8 f4 slots (1/thread), B 64x8 f4 slots (2/thread)
    const int ar = tid >> 3;            // 0..31
    const int aq = (tid & 7) * 4;       // k word
    const int br = tid >> 2;            // 0..63 (first of 2)
    const int bq = (tid & 3) * 8;       // two f4 at bq, bq+4

    auto load_stage = [&](int k0, int s) {
        cp_async16(&As[s][ar * LDA + aq], &g_men[(brow0 + ar) * K2 + k0 + aq]);
        cp_async16(&Bs[s][br * LDA + bq],     &L[(bcol0 + br) * K2 + k0 + bq]);
        cp_async16(&Bs[s][br * LDA + bq + 4], &L[(bcol0 + br) * K2 + k0 + bq + 4]);
        CP_COMMIT();
    };

    float acc[2][4];
#pragma unroll
    for (int j = 0; j < 2; ++j)
#pragma unroll
        for (int v = 0; v < 4; ++v) acc[j][v] = 0.0f;

    load_stage(0, 0);

#pragma unroll
    for (int it = 0; it < K2 / BK; ++it) {
        const int s = it & 1;
        if (it + 1 < K2 / BK) {
            load_stage((it + 1) * BK, s ^ 1);
            CP_WAIT1();
        } else {
            CP_WAIT0();
        }
        __syncthreads();

#pragma unroll
        for (int ks = 0; ks < BK; ks += 8) {
            const int r = wr * 16 + gp;
            const uint32_t a0 = f2tf32(As[s][r * LDA + ks + tg]);
            const uint32_t a1 = f2tf32(As[s][(r + 8) * LDA + ks + tg]);
            const uint32_t a2 = f2tf32(As[s][r * LDA + ks + tg + 4]);
            const uint32_t a3 = f2tf32(As[s][(r + 8) * LDA + ks + tg + 4]);
#pragma unroll
            for (int nt = 0; nt < 2; ++nt) {
                const int n = wc * 16 + nt * 8 + gp;
                const uint32_t b0 = f2tf32(Bs[s][n * LDA + ks + tg]);
                const uint32_t b1 = f2tf32(Bs[s][n * LDA + ks + tg + 4]);
                mma_tf32(acc[nt], a0, a1, a2, a3, b0, b1);
            }
        }
        __syncthreads();
    }

    // epilogue
#pragma unroll
    for (int nt = 0; nt < 2; ++nt) {
        const int row = brow0 + wr * 16 + gp;
        const int col = bcol0 + wc * 16 + nt * 8 + tg * 2;
        float2* o0 = reinterpret_cast<float2*>(&out[row * 128 + col]);
        float2* o1 = reinterpret_cast<float2*>(&out[(row + 8) * 128 + col]);
        *o0 = make_float2(acc[nt][0], acc[nt][1]);
        *o1 = make_float2(acc[nt][2], acc[nt][3]);
    }
}

// ---------------------------------------------------------------------------
extern "C" void kernel_launch(void* const* d_in, const int* in_sizes, int n_in,
                              void* d_out, int out_size)
{
    const int*   feat = (const int*)d_in[0];
    const int*   offs = (const int*)d_in[1];
    const float* W    = (const float*)d_in[2];
    const float* L    = (const float*)d_in[3];
    float*       out  = (float*)d_out;

    const int T = in_sizes[0];
    const int B = in_sizes[1];

    bag_reduce_kernel<<<B, 256>>>(feat, offs, W, T, B);

    dim3 grid(B / BM, 128 / BN);
    men_gemm_kernel<<<grid, 256>>>(L, out, B);
}

// round 7
// speedup vs baseline: 1.0572x; 1.0572x over previous
#include <cuda_runtime.h>
#include <cuda_bf16.h>
#include <cfloat>
#include <cstdint>

// ---------------------------------------------------------------------------
// EmbeddingBag mean||max (B=8192 bags over T=409600 tokens, D=128) + Linear
//   feature_seq : int32 [T]
//   offset_seq  : int32 [B]   (sorted bag starts, offs[0]==0)
//   W           : f32   [VOCAB, 128]
//   L           : f32   [128, 256]
//   out         : f32   [B, 128] = concat(mean, max) @ L^T
// ---------------------------------------------------------------------------

#define D 128
#define K2 256
#define MAX_B 8192

__device__ __align__(16) float g_men[MAX_B * K2];   // [B, 256] scratch

// ============================================================================
// Kernel 1: block-per-bag, 8 warps take contiguous chunks; smem combine.
// At the chip L2-bandwidth floor (~210MB of gathered W rows through LTS).
// ============================================================================
__global__ void __launch_bounds__(256) bag_reduce_kernel(
    const int* __restrict__ feat,
    const int* __restrict__ offs,
    const float* __restrict__ W,
    int T, int B)
{
    const int bag  = blockIdx.x;
    const int w    = threadIdx.x >> 5;
    const int lane = threadIdx.x & 31;

    const int start = offs[bag];
    const int end   = (bag == B - 1) ? T : offs[bag + 1];
    const int cnt   = end - start;

    const float4* __restrict__ Wv = (const float4*)W;   // row stride = 32 float4

    float4 s = make_float4(0.f, 0.f, 0.f, 0.f);
    float4 m = make_float4(-FLT_MAX, -FLT_MAX, -FLT_MAX, -FLT_MAX);

    const int chunk = (cnt + 7) >> 3;
    const int cs = start + w * chunk;
    const int ce = min(cs + chunk, end);

    int t = cs;
    for (; t + 4 <= ce; t += 4) {
        const int f0 = __ldg(&feat[t + 0]);
        const int f1 = __ldg(&feat[t + 1]);
        const int f2 = __ldg(&feat[t + 2]);
        const int f3 = __ldg(&feat[t + 3]);
        const float4 v0 = __ldg(&Wv[f0 * 32 + lane]);
        const float4 v1 = __ldg(&Wv[f1 * 32 + lane]);
        const float4 v2 = __ldg(&Wv[f2 * 32 + lane]);
        const float4 v3 = __ldg(&Wv[f3 * 32 + lane]);
        s.x += v0.x + v1.x + v2.x + v3.x;
        s.y += v0.y + v1.y + v2.y + v3.y;
        s.z += v0.z + v1.z + v2.z + v3.z;
        s.w += v0.w + v1.w + v2.w + v3.w;
        m.x = fmaxf(m.x, fmaxf(fmaxf(v0.x, v1.x), fmaxf(v2.x, v3.x)));
        m.y = fmaxf(m.y, fmaxf(fmaxf(v0.y, v1.y), fmaxf(v2.y, v3.y)));
        m.z = fmaxf(m.z, fmaxf(fmaxf(v0.z, v1.z), fmaxf(v2.z, v3.z)));
        m.w = fmaxf(m.w, fmaxf(fmaxf(v0.w, v1.w), fmaxf(v2.w, v3.w)));
    }
    // predicated remainder (0..3 tokens) in ONE latency wave instead of up to 3
    const int rem = ce - t;
    if (rem > 0) {
        const int i1 = (rem > 1) ? t + 1 : t;
        const int i2 = (rem > 2) ? t + 2 : t;
        const int f0 = __ldg(&feat[t]);
        const int f1 = __ldg(&feat[i1]);
        const int f2 = __ldg(&feat[i2]);
        const float4 v0 = __ldg(&Wv[f0 * 32 + lane]);
        const float4 v1 = __ldg(&Wv[f1 * 32 + lane]);
        const float4 v2 = __ldg(&Wv[f2 * 32 + lane]);
        const float k1 = (rem > 1) ? 1.f : 0.f;
        const float k2 = (rem > 2) ? 1.f : 0.f;
        s.x += v0.x + k1 * v1.x + k2 * v2.x;
        s.y += v0.y + k1 * v1.y + k2 * v2.y;
        s.z += v0.z + k1 * v1.z + k2 * v2.z;
        s.w += v0.w + k1 * v1.w + k2 * v2.w;
        m.x = fmaxf(m.x, v0.x); m.y = fmaxf(m.y, v0.y);
        m.z = fmaxf(m.z, v0.z); m.w = fmaxf(m.w, v0.w);
        if (rem > 1) {
            m.x = fmaxf(m.x, v1.x); m.y = fmaxf(m.y, v1.y);
            m.z = fmaxf(m.z, v1.z); m.w = fmaxf(m.w, v1.w);
        }
        if (rem > 2) {
            m.x = fmaxf(m.x, v2.x); m.y = fmaxf(m.y, v2.y);
            m.z = fmaxf(m.z, v2.z); m.w = fmaxf(m.w, v2.w);
        }
    }

    __shared__ float4 Ss[8][32];
    __shared__ float4 Sm[8][32];
    Ss[w][lane] = s;
    Sm[w][lane] = m;
    __syncthreads();

    if (threadIdx.x < 32) {
        float4 rs = Ss[0][lane];
        float4 rm = Sm[0][lane];
#pragma unroll
        for (int i = 1; i < 8; ++i) {
            const float4 a = Ss[i][lane];
            const float4 b = Sm[i][lane];
            rs.x += a.x; rs.y += a.y; rs.z += a.z; rs.w += a.w;
            rm.x = fmaxf(rm.x, b.x); rm.y = fmaxf(rm.y, b.y);
            rm.z = fmaxf(rm.z, b.z); rm.w = fmaxf(rm.w, b.w);
        }
        const float inv = 1.0f / fmaxf((float)cnt, 1.0f);
        float4 mean = make_float4(rs.x * inv, rs.y * inv, rs.z * inv, rs.w * inv);
        if (cnt == 0) rm = make_float4(0.f, 0.f, 0.f, 0.f);

        float4* mp = (float4*)g_men;                 // row stride = 64 float4
        mp[bag * 64 + lane]      = mean;             // cols [0,128)
        mp[bag * 64 + 32 + lane] = rm;               // cols [128,256)
    }
}

// ============================================================================
// Kernel 2: C = men @ L^T, mma.sync m16n8k8 tf32 with RAW fp32 operand bits
// (HMMA tf32 reads bits[31:13] -> truncation instead of rna; no cvt instrs).
// BM=64, BN=64, BK=32, 256 threads, grid (128,2)=256 blocks.
// 8 warps as 4x2; warp tile 16x32 = 4 n-tiles. 2-stage cp.async double buffer.
// ============================================================================
#define BM 64
#define BN 64
#define BK 32
#define LDA 36             // padded k-stride (words)

__device__ __forceinline__ void mma_tf32(float c[4],
                                         uint32_t a0, uint32_t a1, uint32_t a2, uint32_t a3,
                                         uint32_t b0, uint32_t b1) {
    asm volatile(
        "mma.sync.aligned.m16n8k8.row.col.f32.tf32.tf32.f32 "
        "{%0,%1,%2,%3}, {%4,%5,%6,%7}, {%8,%9}, {%0,%1,%2,%3};"
        : "+f"(c[0]), "+f"(c[1]), "+f"(c[2]), "+f"(c[3])
        : "r"(a0), "r"(a1), "r"(a2), "r"(a3), "r"(b0), "r"(b1));
}

__device__ __forceinline__ void cp_async16(void* smem_dst, const void* gmem_src) {
    uint32_t a;
    asm("{ .reg .u64 t; cvta.to.shared.u64 t, %1; cvt.u32.u64 %0, t; }"
        : "=r"(a) : "l"(smem_dst));
    asm volatile("cp.async.ca.shared.global [%0], [%1], 16;" :: "r"(a), "l"(gmem_src));
}
#define CP_COMMIT() asm volatile("cp.async.commit_group;" ::: "memory")
#define CP_WAIT1()  asm volatile("cp.async.wait_group 1;" ::: "memory")
#define CP_WAIT0()  asm volatile("cp.async.wait_group 0;" ::: "memory")

__global__ void __launch_bounds__(256) men_gemm_kernel(
    const float* __restrict__ L,
    float* __restrict__ out,
    int B)
{
    __shared__ uint32_t As[2][BM * LDA];   // raw f32 bits
    __shared__ uint32_t Bs[2][BN * LDA];

    const int tid  = threadIdx.x;
    const int wid  = tid >> 5;
    const int lane = tid & 31;
    const int wr   = wid >> 1;          // warp row 0..3 (16 rows each)
    const int wc   = wid & 1;           // warp col 0..1 (32 cols each)
    const int gp   = lane >> 2;
    const int tg   = lane & 3;
    const int brow0 = blockIdx.x * BM;
    const int bcol0 = blockIdx.y * BN;

    // stage loader: A 64x8 f4 slots (2/thread), B 64x8 f4 slots (2/thread)
    const int lr = tid >> 2;            // 0..63
    const int lq = (tid & 3) * 8;       // two f4 at lq, lq+4

    auto load_stage = [&](int k0, int s) {
        cp_async16(&As[s][lr * LDA + lq],     &g_men[(brow0 + lr) * K2 + k0 + lq]);
        cp_async16(&As[s][lr * LDA + lq + 4], &g_men[(brow0 + lr) * K2 + k0 + lq + 4]);
        cp_async16(&Bs[s][lr * LDA + lq],     &L[(bcol0 + lr) * K2 + k0 + lq]);
        cp_async16(&Bs[s][lr * LDA + lq + 4], &L[(bcol0 + lr) * K2 + k0 + lq + 4]);
        CP_COMMIT();
    };

    float acc[4][4];
#pragma unroll
    for (int j = 0; j < 4; ++j)
#pragma unroll
        for (int v = 0; v < 4; ++v) acc[j][v] = 0.0f;

    load_stage(0, 0);

#pragma unroll
    for (int it = 0; it < K2 / BK; ++it) {
        const int s = it & 1;
        if (it + 1 < K2 / BK) {
            load_stage((it + 1) * BK, s ^ 1);
            CP_WAIT1();
        } else {
            CP_WAIT0();
        }
        __syncthreads();

#pragma unroll
        for (int ks = 0; ks < BK; ks += 8) {
            const int r = wr * 16 + gp;
            const uint32_t a0 = As[s][r * LDA + ks + tg];
            const uint32_t a1 = As[s][(r + 8) * LDA + ks + tg];
            const uint32_t a2 = As[s][r * LDA + ks + tg + 4];
            const uint32_t a3 = As[s][(r + 8) * LDA + ks + tg + 4];
#pragma unroll
            for (int nt = 0; nt < 4; ++nt) {
                const int n = wc * 32 + nt * 8 + gp;
                const uint32_t b0 = Bs[s][n * LDA + ks + tg];
                const uint32_t b1 = Bs[s][n * LDA + ks + tg + 4];
                mma_tf32(acc[nt], a0, a1, a2, a3, b0, b1);
            }
        }
        __syncthreads();
    }

    // epilogue
#pragma unroll
    for (int nt = 0; nt < 4; ++nt) {
        const int row = brow0 + wr * 16 + gp;
        const int col = bcol0 + wc * 32 + nt * 8 + tg * 2;
        float2* o0 = reinterpret_cast<float2*>(&out[row * 128 + col]);
        float2* o1 = reinterpret_cast<float2*>(&out[(row + 8) * 128 + col]);
        *o0 = make_float2(acc[nt][0], acc[nt][1]);
        *o1 = make_float2(acc[nt][2], acc[nt][3]);
    }
}

// ---------------------------------------------------------------------------
extern "C" void kernel_launch(void* const* d_in, const int* in_sizes, int n_in,
                              void* d_out, int out_size)
{
    const int*   feat = (const int*)d_in[0];
    const int*   offs = (const int*)d_in[1];
    const float* W    = (const float*)d_in[2];
    const float* L    = (const float*)d_in[3];
    float*       out  = (float*)d_out;

    const int T = in_sizes[0];
    const int B = in_sizes[1];

    bag_reduce_kernel<<<B, 256>>>(feat, offs, W, T, B);

    dim3 grid(B / BM, 128 / BN);
    men_gemm_kernel<<<grid, 256>>>(L, out, B);
}